// round 10
// baseline (speedup 1.0000x reference)
#include <cuda_runtime.h>
#include <cstdint>

// Problem shapes (fixed by the dataset)
#define Bb   8
#define Tt   64
#define Nn   256
#define Dd   128
#define MTOK (Bb*Tt*Nn)     // 131072 tokens
#define K2   256            // 2*D (concat input dim)
#define QKVN 384            // 3*D output cols of fused QKV GEMM

#define S2   132            // smem row stride in float2 units ([k][x] layout); 132 % 16 == 4

// Scratch (device globals; no allocation allowed)
__device__ float g_Wqkv[K2*QKVN];   // packed [256][384] = Wq|Wk|Wv
__device__ float g_bqkv[QKVN];
__device__ float g_Q[MTOK*Dd];
__device__ float g_K[MTOK*Dd];
__device__ float g_V[MTOK*Dd];
__device__ float g_AO[MTOK*Dd];

// ---------------------------------------------------------------------------
__device__ __forceinline__ uint32_t f2tf32(float x) {
    uint32_t r;
    asm("cvt.rna.tf32.f32 %0, %1;" : "=r"(r) : "f"(x));
    return r;
}

// split x into (hi = tf32(x), lo = tf32(x - hi)), both in fp32 containers
__device__ __forceinline__ float2 split_tf32(float x) {
    float hf = __uint_as_float(f2tf32(x));
    float lf = __uint_as_float(f2tf32(x - hf));
    return make_float2(hf, lf);
}

__device__ __forceinline__ void mma8(float* c, const uint32_t* a, const uint32_t* b) {
    asm volatile(
        "mma.sync.aligned.m16n8k8.row.col.f32.tf32.tf32.f32 "
        "{%0,%1,%2,%3}, {%4,%5,%6,%7}, {%8,%9}, {%0,%1,%2,%3};"
        : "+f"(c[0]), "+f"(c[1]), "+f"(c[2]), "+f"(c[3])
        : "r"(a[0]), "r"(a[1]), "r"(a[2]), "r"(a[3]),
          "r"(b[0]), "r"(b[1]));
}

// ---------------------------------------------------------------------------
// Kernel 0: pack Wq/Wk/Wv ([256,128] each, row-major) into g_Wqkv [256,384]
// ---------------------------------------------------------------------------
__global__ void pack_w(const float* __restrict__ Wq, const float* __restrict__ bq,
                       const float* __restrict__ Wk, const float* __restrict__ bk,
                       const float* __restrict__ Wv, const float* __restrict__ bv) {
    int i = blockIdx.x * blockDim.x + threadIdx.x;
    if (i < K2 * Dd) {
        int k = i / Dd, j = i % Dd;
        g_Wqkv[k*QKVN + j        ] = Wq[i];
        g_Wqkv[k*QKVN + Dd   + j ] = Wk[i];
        g_Wqkv[k*QKVN + 2*Dd + j ] = Wv[i];
    }
    if (i < Dd) {
        g_bqkv[i]        = bq[i];
        g_bqkv[Dd + i]   = bk[i];
        g_bqkv[2*Dd + i] = bv[i];
    }
}

// ---------------------------------------------------------------------------
// 3xTF32 tensor-core GEMM core. BM=BN=128, BK=8, 128 threads, 4 warps (2x2),
// 64x64 per warp. Smem [k][x] float2 {hi,lo}, stride S2.
// ---------------------------------------------------------------------------

struct TileRegs {
    float4 a0, a1;               // A rows ar, ar+64 (4 k each)
    float2 b0, b1, b2, b3;       // B: rows (bw, bw+4) x col-pairs (2bl, 2bl+64)
};

// A store: thread owns row 'row', k = ak4..ak4+3, rotation by par keeps
// 64-bit store phases conflict-free.
__device__ __forceinline__ void storeA4(float2* sA, int row, int ak4, int par, float4 v) {
    const float vv[4] = {v.x, v.y, v.z, v.w};
    #pragma unroll
    for (int ii = 0; ii < 4; ii++) {
        int q = (ii + 2*par) & 3;
        sA[(ak4 + q) * S2 + row] = split_tf32(vv[q]);
    }
}

// B store: one global float2 (cols n, n+1) -> one STS.128 of {h0,l0,h1,l1}
__device__ __forceinline__ void storeB2(float2* dst, float2 gv) {
    float2 a = split_tf32(gv.x);
    float2 b = split_tf32(gv.y);
    *(float4*)dst = make_float4(a.x, a.y, b.x, b.y);
}

#define GEMM_COMPUTE(sA, sB)                                                 \
    {                                                                        \
        uint32_t Ah[4][4], Al[4][4], Bh[8][2], Bl[8][2];                     \
        _Pragma("unroll")                                                    \
        for (int im = 0; im < 4; im++) {                                     \
            int m = wm + im*16 + g;                                          \
            float2 f0 = (sA)[ t   *S2 + m    ];                              \
            float2 f1 = (sA)[ t   *S2 + m + 8];                              \
            float2 f2 = (sA)[(t+4)*S2 + m    ];                              \
            float2 f3 = (sA)[(t+4)*S2 + m + 8];                              \
            Ah[im][0] = __float_as_uint(f0.x); Al[im][0] = __float_as_uint(f0.y); \
            Ah[im][1] = __float_as_uint(f1.x); Al[im][1] = __float_as_uint(f1.y); \
            Ah[im][2] = __float_as_uint(f2.x); Al[im][2] = __float_as_uint(f2.y); \
            Ah[im][3] = __float_as_uint(f3.x); Al[im][3] = __float_as_uint(f3.y); \
        }                                                                    \
        _Pragma("unroll")                                                    \
        for (int in = 0; in < 8; in++) {                                     \
            int n = wn + in*8 + g;                                           \
            float2 e0 = (sB)[ t   *S2 + n];                                  \
            float2 e1 = (sB)[(t+4)*S2 + n];                                  \
            Bh[in][0] = __float_as_uint(e0.x); Bl[in][0] = __float_as_uint(e0.y); \
            Bh[in][1] = __float_as_uint(e1.x); Bl[in][1] = __float_as_uint(e1.y); \
        }                                                                    \
        _Pragma("unroll")                                                    \
        for (int im = 0; im < 4; im++)                                       \
            _Pragma("unroll")                                                \
            for (int in = 0; in < 8; in++) mma8(acc[im][in], Ah[im], Bh[in]);\
        _Pragma("unroll")                                                    \
        for (int im = 0; im < 4; im++)                                       \
            _Pragma("unroll")                                                \
            for (int in = 0; in < 8; in++) mma8(acc[im][in], Al[im], Bh[in]);\
        _Pragma("unroll")                                                    \
        for (int im = 0; im < 4; im++)                                       \
            _Pragma("unroll")                                                \
            for (int in = 0; in < 8; in++) mma8(acc[im][in], Ah[im], Bl[in]);\
    }

// store one slab's worth of loaded tile registers into smem buffer
#define STORE_TILE(buf)                                                      \
    storeA4(sA2[buf], ar,      ak4, par, tr.a0);                             \
    storeA4(sA2[buf], ar + 64, ak4, par, tr.a1);                             \
    storeB2(&sB2[buf][ bw   *S2 + 2*bl     ], tr.b0);                        \
    storeB2(&sB2[buf][ bw   *S2 + 2*bl + 64], tr.b1);                        \
    storeB2(&sB2[buf][(bw+4)*S2 + 2*bl     ], tr.b2);                        \
    storeB2(&sB2[buf][(bw+4)*S2 + 2*bl + 64], tr.b3);

// ---------------------------------------------------------------------------
// Kernel 1: QKV GEMM (3xTF32).  relu([X|STE] @ Wqkv + b) -> g_Q/g_K/g_V
// ---------------------------------------------------------------------------
__global__ __launch_bounds__(128) void qkv_gemm_tc(const float* __restrict__ X,
                                                   const float* __restrict__ STE) {
    __shared__ float2 sA2[2][8*S2];
    __shared__ float2 sB2[2][8*S2];

    const int tid = threadIdx.x;
    const int lane = tid & 31;
    const int wid = tid >> 5;
    const int g = lane >> 2, t = lane & 3;
    const int wm = (wid >> 1) * 64, wn = (wid & 1) * 64;
    const int m0 = blockIdx.x * 128;
    const int j0 = blockIdx.y * 128;

    // A loader coords
    const int ar  = tid >> 1;          // A row (also +64)
    const int par = tid & 1;
    const int ak4 = par * 4;
    // B loader coords: warp bw owns k-rows {bw, bw+4}; lane bl -> col pair 2bl (+64)
    const int bw = wid;                // 0..3
    const int bl = lane;               // 0..31

    float acc[4][8][4];
    #pragma unroll
    for (int im = 0; im < 4; im++)
        #pragma unroll
        for (int in = 0; in < 8; in++)
            #pragma unroll
            for (int r = 0; r < 4; r++) acc[im][in][r] = 0.f;

    const int NIT = K2 / 8;   // 32

    TileRegs tr;
    // preload slab 0
    {
        tr.a0 = *(const float4*)&X[(size_t)(m0 + ar) * Dd + ak4];
        tr.a1 = *(const float4*)&X[(size_t)(m0 + ar + 64) * Dd + ak4];
        tr.b0 = *(const float2*)&g_Wqkv[(size_t) bw      * QKVN + j0 + 2*bl];
        tr.b1 = *(const float2*)&g_Wqkv[(size_t) bw      * QKVN + j0 + 2*bl + 64];
        tr.b2 = *(const float2*)&g_Wqkv[(size_t)(bw + 4) * QKVN + j0 + 2*bl];
        tr.b3 = *(const float2*)&g_Wqkv[(size_t)(bw + 4) * QKVN + j0 + 2*bl + 64];
    }
    STORE_TILE(0);
    __syncthreads();

    for (int it = 0; it < NIT; it++) {
        const int cur = it & 1;
        const bool has_next = (it + 1 < NIT);
        if (has_next) {
            int k0 = (it + 1) * 8;
            const float* src = (k0 < Dd) ? X : STE;
            int gk = (k0 & (Dd - 1)) + ak4;
            tr.a0 = *(const float4*)&src[(size_t)(m0 + ar) * Dd + gk];
            tr.a1 = *(const float4*)&src[(size_t)(m0 + ar + 64) * Dd + gk];
            tr.b0 = *(const float2*)&g_Wqkv[(size_t)(k0 + bw    ) * QKVN + j0 + 2*bl];
            tr.b1 = *(const float2*)&g_Wqkv[(size_t)(k0 + bw    ) * QKVN + j0 + 2*bl + 64];
            tr.b2 = *(const float2*)&g_Wqkv[(size_t)(k0 + bw + 4) * QKVN + j0 + 2*bl];
            tr.b3 = *(const float2*)&g_Wqkv[(size_t)(k0 + bw + 4) * QKVN + j0 + 2*bl + 64];
        }

        GEMM_COMPUTE(sA2[cur], sB2[cur]);

        if (has_next) {
            const int nxt = cur ^ 1;
            STORE_TILE(nxt);
        }
        __syncthreads();
    }

    // epilogue: bias + relu; whole 128-col tile -> exactly one of Q/K/V
    float* dst = (j0 == 0) ? g_Q : ((j0 == Dd) ? g_K : g_V);
    #pragma unroll
    for (int im = 0; im < 4; im++) {
        int r0 = m0 + wm + im * 16 + g;
        #pragma unroll
        for (int in = 0; in < 8; in++) {
            int c = wn + in * 8 + 2 * t;   // local col (0..127), even
            float b0v = g_bqkv[j0 + c], b1v = g_bqkv[j0 + c + 1];
            float2 o;
            o.x = fmaxf(acc[im][in][0] + b0v, 0.f);
            o.y = fmaxf(acc[im][in][1] + b1v, 0.f);
            *(float2*)&dst[(size_t)r0 * Dd + c] = o;
            o.x = fmaxf(acc[im][in][2] + b0v, 0.f);
            o.y = fmaxf(acc[im][in][3] + b1v, 0.f);
            *(float2*)&dst[(size_t)(r0 + 8) * Dd + c] = o;
        }
    }
}

// ---------------------------------------------------------------------------
// Kernel 2: causal attention. 2 instances per 128-thread block. (fp32)
// ---------------------------------------------------------------------------
__global__ __launch_bounds__(128) void attn_kernel() {
    __shared__ float sK[2][64][9];
    __shared__ float sV[2][64][9];
    __shared__ float sS[2][64][65];

    const int li   = threadIdx.x >> 6;
    const int inst = blockIdx.x * 2 + li;
    const int b = inst >> 12;
    const int r = inst & 4095;
    const int n = r >> 4;
    const int c = r & 15;
    const int t = threadIdx.x & 63;

    const size_t base = ((((size_t)b * Tt + t) * Nn + n) * Dd) + (size_t)c * 8;

    float q[8];
    {
        float4 k0 = *(const float4*)&g_K[base];
        float4 k1 = *(const float4*)&g_K[base + 4];
        float4 v0 = *(const float4*)&g_V[base];
        float4 v1 = *(const float4*)&g_V[base + 4];
        float4 q0 = *(const float4*)&g_Q[base];
        float4 q1 = *(const float4*)&g_Q[base + 4];
        sK[li][t][0]=k0.x; sK[li][t][1]=k0.y; sK[li][t][2]=k0.z; sK[li][t][3]=k0.w;
        sK[li][t][4]=k1.x; sK[li][t][5]=k1.y; sK[li][t][6]=k1.z; sK[li][t][7]=k1.w;
        sV[li][t][0]=v0.x; sV[li][t][1]=v0.y; sV[li][t][2]=v0.z; sV[li][t][3]=v0.w;
        sV[li][t][4]=v1.x; sV[li][t][5]=v1.y; sV[li][t][6]=v1.z; sV[li][t][7]=v1.w;
        q[0]=q0.x; q[1]=q0.y; q[2]=q0.z; q[3]=q0.w;
        q[4]=q1.x; q[5]=q1.y; q[6]=q1.z; q[7]=q1.w;
    }
    __syncthreads();

    float mx = -1e30f;
    for (int s = 0; s <= t; s++) {
        float d = 0.f;
        #pragma unroll
        for (int h = 0; h < 8; h++) d = fmaf(q[h], sK[li][s][h], d);
        d *= 0.25f;
        sS[li][t][s] = d;
        mx = fmaxf(mx, d);
    }
    float denom = 0.f;
    float acc[8];
    #pragma unroll
    for (int h = 0; h < 8; h++) acc[h] = 0.f;
    for (int s = 0; s <= t; s++) {
        float p = __expf(sS[li][t][s] - mx);
        denom += p;
        #pragma unroll
        for (int h = 0; h < 8; h++) acc[h] = fmaf(p, sV[li][s][h], acc[h]);
    }
    float inv = 1.f / denom;
    float4 o0 = make_float4(acc[0]*inv, acc[1]*inv, acc[2]*inv, acc[3]*inv);
    float4 o1 = make_float4(acc[4]*inv, acc[5]*inv, acc[6]*inv, acc[7]*inv);
    *(float4*)&g_AO[base]     = o0;
    *(float4*)&g_AO[base + 4] = o1;
}

// ---------------------------------------------------------------------------
// Kernel 3: output projection (3xTF32).  out = relu(AO @ Wo + bo)
// ---------------------------------------------------------------------------
__global__ __launch_bounds__(128) void out_gemm_tc(const float* __restrict__ Wo,
                                                   const float* __restrict__ bo,
                                                   float* __restrict__ out) {
    __shared__ float2 sA2[2][8*S2];
    __shared__ float2 sB2[2][8*S2];

    const int tid = threadIdx.x;
    const int lane = tid & 31;
    const int wid = tid >> 5;
    const int g = lane >> 2, t = lane & 3;
    const int wm = (wid >> 1) * 64, wn = (wid & 1) * 64;
    const int m0 = blockIdx.x * 128;

    const int ar  = tid >> 1;
    const int par = tid & 1;
    const int ak4 = par * 4;
    const int bw = wid;
    const int bl = lane;

    float acc[4][8][4];
    #pragma unroll
    for (int im = 0; im < 4; im++)
        #pragma unroll
        for (int in = 0; in < 8; in++)
            #pragma unroll
            for (int r = 0; r < 4; r++) acc[im][in][r] = 0.f;

    const int NIT = Dd / 8;   // 16

    TileRegs tr;
    tr.a0 = *(const float4*)&g_AO[(size_t)(m0 + ar) * Dd + ak4];
    tr.a1 = *(const float4*)&g_AO[(size_t)(m0 + ar + 64) * Dd + ak4];
    tr.b0 = *(const float2*)&Wo[(size_t) bw      * Dd + 2*bl];
    tr.b1 = *(const float2*)&Wo[(size_t) bw      * Dd + 2*bl + 64];
    tr.b2 = *(const float2*)&Wo[(size_t)(bw + 4) * Dd + 2*bl];
    tr.b3 = *(const float2*)&Wo[(size_t)(bw + 4) * Dd + 2*bl + 64];
    STORE_TILE(0);
    __syncthreads();

    for (int it = 0; it < NIT; it++) {
        const int cur = it & 1;
        const bool has_next = (it + 1 < NIT);
        if (has_next) {
            int k0 = (it + 1) * 8;
            tr.a0 = *(const float4*)&g_AO[(size_t)(m0 + ar) * Dd + k0 + ak4];
            tr.a1 = *(const float4*)&g_AO[(size_t)(m0 + ar + 64) * Dd + k0 + ak4];
            tr.b0 = *(const float2*)&Wo[(size_t)(k0 + bw    ) * Dd + 2*bl];
            tr.b1 = *(const float2*)&Wo[(size_t)(k0 + bw    ) * Dd + 2*bl + 64];
            tr.b2 = *(const float2*)&Wo[(size_t)(k0 + bw + 4) * Dd + 2*bl];
            tr.b3 = *(const float2*)&Wo[(size_t)(k0 + bw + 4) * Dd + 2*bl + 64];
        }

        GEMM_COMPUTE(sA2[cur], sB2[cur]);

        if (has_next) {
            const int nxt = cur ^ 1;
            STORE_TILE(nxt);
        }
        __syncthreads();
    }

    #pragma unroll
    for (int im = 0; im < 4; im++) {
        int r0 = m0 + wm + im * 16 + g;
        #pragma unroll
        for (int in = 0; in < 8; in++) {
            int c = wn + in * 8 + 2 * t;
            float b0v = bo[c], b1v = bo[c + 1];
            float2 o;
            o.x = fmaxf(acc[im][in][0] + b0v, 0.f);
            o.y = fmaxf(acc[im][in][1] + b1v, 0.f);
            *(float2*)&out[(size_t)r0 * Dd + c] = o;
            o.x = fmaxf(acc[im][in][2] + b0v, 0.f);
            o.y = fmaxf(acc[im][in][3] + b1v, 0.f);
            *(float2*)&out[(size_t)(r0 + 8) * Dd + c] = o;
        }
    }
}

// ---------------------------------------------------------------------------
extern "C" void kernel_launch(void* const* d_in, const int* in_sizes, int n_in,
                              void* d_out, int out_size) {
    const float* X   = (const float*)d_in[0];
    const float* STE = (const float*)d_in[1];
    const float* Wq  = (const float*)d_in[2];
    const float* bq  = (const float*)d_in[3];
    const float* Wk  = (const float*)d_in[4];
    const float* bk  = (const float*)d_in[5];
    const float* Wv  = (const float*)d_in[6];
    const float* bv  = (const float*)d_in[7];
    const float* Wo  = (const float*)d_in[8];
    const float* bo  = (const float*)d_in[9];
    float* out = (float*)d_out;

    pack_w<<<128, 256>>>(Wq, bq, Wk, bk, Wv, bv);

    dim3 gA(MTOK / 128, QKVN / 128);        // 1024 x 3
    qkv_gemm_tc<<<gA, 128>>>(X, STE);

    attn_kernel<<<Bb * Nn * 8, 128>>>();    // 32768 instances, 2 per block

    out_gemm_tc<<<MTOK / 128, 128>>>(Wo, bo, out);
}

// round 12
// speedup vs baseline: 1.3827x; 1.3827x over previous
#include <cuda_runtime.h>
#include <cuda_bf16.h>
#include <cstdint>

// Problem shapes (fixed by the dataset)
#define Bb   8
#define Tt   64
#define Nn   256
#define Dd   128
#define MTOK (Bb*Tt*Nn)     // 131072 tokens
#define K2   256            // 2*D (concat input dim)
#define QKVN 384            // 3*D output cols of fused QKV GEMM

#define SPAD 136            // smem row stride in 4B words ([kpair][x] layout)

// Scratch (device globals; no allocation allowed)
__device__ float g_Wqkv[K2*QKVN];   // packed [256][384] = Wq|Wk|Wv
__device__ float g_bqkv[QKVN];
__device__ float g_Q[MTOK*Dd];
__device__ float g_K[MTOK*Dd];
__device__ float g_V[MTOK*Dd];
__device__ float g_AO[MTOK*Dd];

// ---------------------------------------------------------------------------
// bf16 double-split: x = hi + lo + O(2^-17 x). Pack k-pairs (x0=k even low
// half, x1=k odd high half) for m16n8k16 fragments.
__device__ __forceinline__ void split2(float x0, float x1, uint32_t& hi, uint32_t& lo) {
    __nv_bfloat16 h0 = __float2bfloat16(x0);
    __nv_bfloat16 h1 = __float2bfloat16(x1);
    __nv_bfloat16 l0 = __float2bfloat16(x0 - __bfloat162float(h0));
    __nv_bfloat16 l1 = __float2bfloat16(x1 - __bfloat162float(h1));
    __nv_bfloat162 hp = __halves2bfloat162(h0, h1);
    __nv_bfloat162 lp = __halves2bfloat162(l0, l1);
    hi = *reinterpret_cast<uint32_t*>(&hp);
    lo = *reinterpret_cast<uint32_t*>(&lp);
}

__device__ __forceinline__ void mma16(float* c, const uint32_t* a, const uint32_t* b) {
    asm volatile(
        "mma.sync.aligned.m16n8k16.row.col.f32.bf16.bf16.f32 "
        "{%0,%1,%2,%3}, {%4,%5,%6,%7}, {%8,%9}, {%0,%1,%2,%3};"
        : "+f"(c[0]), "+f"(c[1]), "+f"(c[2]), "+f"(c[3])
        : "r"(a[0]), "r"(a[1]), "r"(a[2]), "r"(a[3]),
          "r"(b[0]), "r"(b[1]));
}

// ---------------------------------------------------------------------------
// Kernel 0: pack Wq/Wk/Wv ([256,128] each, row-major) into g_Wqkv [256,384]
// ---------------------------------------------------------------------------
__global__ void pack_w(const float* __restrict__ Wq, const float* __restrict__ bq,
                       const float* __restrict__ Wk, const float* __restrict__ bk,
                       const float* __restrict__ Wv, const float* __restrict__ bv) {
    int i = blockIdx.x * blockDim.x + threadIdx.x;
    if (i < K2 * Dd) {
        int k = i / Dd, j = i % Dd;
        g_Wqkv[k*QKVN + j        ] = Wq[i];
        g_Wqkv[k*QKVN + Dd   + j ] = Wk[i];
        g_Wqkv[k*QKVN + 2*Dd + j ] = Wv[i];
    }
    if (i < Dd) {
        g_bqkv[i]        = bq[i];
        g_bqkv[Dd + i]   = bk[i];
        g_bqkv[2*Dd + i] = bv[i];
    }
}

// ---------------------------------------------------------------------------
// 3-term bf16 tensor-core GEMM core.  BM=BN=128, BK=16, 128 threads,
// 4 warps (2x2), 64x64 per warp, m16n8k16.  Smem [kpair][x] (uint32 = bf16x2),
// stride SPAD; separate hi/lo arrays (R9-proven layout).
// ---------------------------------------------------------------------------

// A store: thread owns row 'row', kpairs par*4..par*4+3 (from two float4s
// holding k = par*8..par*8+7).  Rotation by par keeps phases conflict-free.
__device__ __forceinline__ void storeA(uint32_t* sAh, uint32_t* sAl,
                                       int row, int par, float4 v0, float4 v1) {
    const float vv[8] = {v0.x, v0.y, v0.z, v0.w, v1.x, v1.y, v1.z, v1.w};
    #pragma unroll
    for (int ii = 0; ii < 4; ii++) {
        int q = (ii + 2*par) & 3;                 // kpair within this thread's 4
        uint32_t h, l;
        split2(vv[2*q], vv[2*q + 1], h, l);
        sAh[(par*4 + q)*SPAD + row] = h;
        sAl[(par*4 + q)*SPAD + row] = l;
    }
}

// B store: thread owns kpair bkp, cols bn0..bn0+7; r0 = k even row, r1 = k odd.
__device__ __forceinline__ void storeB(uint32_t* sBh, uint32_t* sBl,
                                       int bkp, int bn0, int c4,
                                       float4 r0a, float4 r0b, float4 r1a, float4 r1b) {
    const float r0[8] = {r0a.x,r0a.y,r0a.z,r0a.w, r0b.x,r0b.y,r0b.z,r0b.w};
    const float r1[8] = {r1a.x,r1a.y,r1a.z,r1a.w, r1b.x,r1b.y,r1b.z,r1b.w};
    #pragma unroll
    for (int ii = 0; ii < 8; ii++) {
        int j = (ii + 2*c4) & 7;
        uint32_t h, l;
        split2(r0[j], r1[j], h, l);
        sBh[bkp*SPAD + bn0 + j] = h;
        sBl[bkp*SPAD + bn0 + j] = l;
    }
}

#define GEMM_COMPUTE(sAh, sAl, sBh, sBl)                                     \
    {                                                                        \
        uint32_t Ah[4][4], Al[4][4], Bh[8][2], Bl[8][2];                     \
        _Pragma("unroll")                                                    \
        for (int im = 0; im < 4; im++) {                                     \
            int m = wm + im*16 + g;                                          \
            Ah[im][0] = (sAh)[ t   *SPAD + m    ];                           \
            Ah[im][1] = (sAh)[ t   *SPAD + m + 8];                           \
            Ah[im][2] = (sAh)[(t+4)*SPAD + m    ];                           \
            Ah[im][3] = (sAh)[(t+4)*SPAD + m + 8];                           \
            Al[im][0] = (sAl)[ t   *SPAD + m    ];                           \
            Al[im][1] = (sAl)[ t   *SPAD + m + 8];                           \
            Al[im][2] = (sAl)[(t+4)*SPAD + m    ];                           \
            Al[im][3] = (sAl)[(t+4)*SPAD + m + 8];                           \
        }                                                                    \
        _Pragma("unroll")                                                    \
        for (int in = 0; in < 8; in++) {                                     \
            int n = wn + in*8 + g;                                           \
            Bh[in][0] = (sBh)[ t   *SPAD + n];                               \
            Bh[in][1] = (sBh)[(t+4)*SPAD + n];                               \
            Bl[in][0] = (sBl)[ t   *SPAD + n];                               \
            Bl[in][1] = (sBl)[(t+4)*SPAD + n];                               \
        }                                                                    \
        _Pragma("unroll")                                                    \
        for (int im = 0; im < 4; im++)                                       \
            _Pragma("unroll")                                                \
            for (int in = 0; in < 8; in++) mma16(acc[im][in], Ah[im], Bh[in]);\
        _Pragma("unroll")                                                    \
        for (int im = 0; im < 4; im++)                                       \
            _Pragma("unroll")                                                \
            for (int in = 0; in < 8; in++) mma16(acc[im][in], Al[im], Bh[in]);\
        _Pragma("unroll")                                                    \
        for (int im = 0; im < 4; im++)                                       \
            _Pragma("unroll")                                                \
            for (int in = 0; in < 8; in++) mma16(acc[im][in], Ah[im], Bl[in]);\
    }

#define STORE_TILE(buf)                                                      \
    storeA(sAh[buf], sAl[buf], ar,      par, tr_a0, tr_a1);                  \
    storeA(sAh[buf], sAl[buf], ar + 64, par, tr_a2, tr_a3);                  \
    storeB(sBh[buf], sBl[buf], bkp, bn0, bc4, tr_b0, tr_b1, tr_b2, tr_b3);

// ---------------------------------------------------------------------------
// Kernel 1: QKV GEMM (bf16 3-term).  relu([X|STE] @ Wqkv + b) -> g_Q/g_K/g_V
// ---------------------------------------------------------------------------
__global__ __launch_bounds__(128) void qkv_gemm_tc(const float* __restrict__ X,
                                                   const float* __restrict__ STE) {
    __shared__ uint32_t sAh[2][8*SPAD], sAl[2][8*SPAD];
    __shared__ uint32_t sBh[2][8*SPAD], sBl[2][8*SPAD];

    const int tid = threadIdx.x;
    const int lane = tid & 31;
    const int wid = tid >> 5;
    const int g = lane >> 2, t = lane & 3;
    const int wm = (wid >> 1) * 64, wn = (wid & 1) * 64;
    const int m0 = blockIdx.x * 128;
    const int j0 = blockIdx.y * 128;

    // A loader: row ar (and ar+64), k = par*8..par*8+7
    const int ar  = tid >> 1;
    const int par = tid & 1;
    // B loader: kpair bkp (k rows 2bkp, 2bkp+1), cols bn0..bn0+7
    const int bkp = tid >> 4;            // 0..7
    const int bn0 = (tid & 15) * 8;
    const int bc4 = (tid & 15) >> 2;

    float acc[4][8][4];
    #pragma unroll
    for (int im = 0; im < 4; im++)
        #pragma unroll
        for (int in = 0; in < 8; in++)
            #pragma unroll
            for (int r = 0; r < 4; r++) acc[im][in][r] = 0.f;

    const int NIT = K2 / 16;   // 16 slabs

    float4 tr_a0, tr_a1, tr_a2, tr_a3, tr_b0, tr_b1, tr_b2, tr_b3;
    // preload slab 0 (k0 = 0, inside X)
    {
        const float* src = X;
        int gk = par * 8;
        tr_a0 = *(const float4*)&src[(size_t)(m0 + ar) * Dd + gk];
        tr_a1 = *(const float4*)&src[(size_t)(m0 + ar) * Dd + gk + 4];
        tr_a2 = *(const float4*)&src[(size_t)(m0 + ar + 64) * Dd + gk];
        tr_a3 = *(const float4*)&src[(size_t)(m0 + ar + 64) * Dd + gk + 4];
        tr_b0 = *(const float4*)&g_Wqkv[(size_t)(2*bkp    ) * QKVN + j0 + bn0];
        tr_b1 = *(const float4*)&g_Wqkv[(size_t)(2*bkp    ) * QKVN + j0 + bn0 + 4];
        tr_b2 = *(const float4*)&g_Wqkv[(size_t)(2*bkp + 1) * QKVN + j0 + bn0];
        tr_b3 = *(const float4*)&g_Wqkv[(size_t)(2*bkp + 1) * QKVN + j0 + bn0 + 4];
    }
    STORE_TILE(0);
    __syncthreads();

    for (int it = 0; it < NIT; it++) {
        const int cur = it & 1;
        const bool has_next = (it + 1 < NIT);
        if (has_next) {
            int k0 = (it + 1) * 16;
            const float* src = (k0 < Dd) ? X : STE;
            int gk = (k0 & (Dd - 1)) + par * 8;
            tr_a0 = *(const float4*)&src[(size_t)(m0 + ar) * Dd + gk];
            tr_a1 = *(const float4*)&src[(size_t)(m0 + ar) * Dd + gk + 4];
            tr_a2 = *(const float4*)&src[(size_t)(m0 + ar + 64) * Dd + gk];
            tr_a3 = *(const float4*)&src[(size_t)(m0 + ar + 64) * Dd + gk + 4];
            tr_b0 = *(const float4*)&g_Wqkv[(size_t)(k0 + 2*bkp    ) * QKVN + j0 + bn0];
            tr_b1 = *(const float4*)&g_Wqkv[(size_t)(k0 + 2*bkp    ) * QKVN + j0 + bn0 + 4];
            tr_b2 = *(const float4*)&g_Wqkv[(size_t)(k0 + 2*bkp + 1) * QKVN + j0 + bn0];
            tr_b3 = *(const float4*)&g_Wqkv[(size_t)(k0 + 2*bkp + 1) * QKVN + j0 + bn0 + 4];
        }

        GEMM_COMPUTE(sAh[cur], sAl[cur], sBh[cur], sBl[cur]);

        if (has_next) {
            const int nxt = cur ^ 1;
            STORE_TILE(nxt);
        }
        __syncthreads();
    }

    // epilogue: bias + relu; whole 128-col tile -> exactly one of Q/K/V
    float* dst = (j0 == 0) ? g_Q : ((j0 == Dd) ? g_K : g_V);
    #pragma unroll
    for (int im = 0; im < 4; im++) {
        int r0 = m0 + wm + im * 16 + g;
        #pragma unroll
        for (int in = 0; in < 8; in++) {
            int c = wn + in * 8 + 2 * t;   // local col (0..127), even
            float b0v = g_bqkv[j0 + c], b1v = g_bqkv[j0 + c + 1];
            float2 o;
            o.x = fmaxf(acc[im][in][0] + b0v, 0.f);
            o.y = fmaxf(acc[im][in][1] + b1v, 0.f);
            *(float2*)&dst[(size_t)r0 * Dd + c] = o;
            o.x = fmaxf(acc[im][in][2] + b0v, 0.f);
            o.y = fmaxf(acc[im][in][3] + b1v, 0.f);
            *(float2*)&dst[(size_t)(r0 + 8) * Dd + c] = o;
        }
    }
}

// ---------------------------------------------------------------------------
// Kernel 2: causal attention. 2 instances per 128-thread block. (fp32)
// ---------------------------------------------------------------------------
__global__ __launch_bounds__(128) void attn_kernel() {
    __shared__ float sK[2][64][9];
    __shared__ float sV[2][64][9];
    __shared__ float sS[2][64][65];

    const int li   = threadIdx.x >> 6;
    const int inst = blockIdx.x * 2 + li;
    const int b = inst >> 12;
    const int r = inst & 4095;
    const int n = r >> 4;
    const int c = r & 15;
    const int t = threadIdx.x & 63;

    const size_t base = ((((size_t)b * Tt + t) * Nn + n) * Dd) + (size_t)c * 8;

    float q[8];
    {
        float4 k0 = *(const float4*)&g_K[base];
        float4 k1 = *(const float4*)&g_K[base + 4];
        float4 v0 = *(const float4*)&g_V[base];
        float4 v1 = *(const float4*)&g_V[base + 4];
        float4 q0 = *(const float4*)&g_Q[base];
        float4 q1 = *(const float4*)&g_Q[base + 4];
        sK[li][t][0]=k0.x; sK[li][t][1]=k0.y; sK[li][t][2]=k0.z; sK[li][t][3]=k0.w;
        sK[li][t][4]=k1.x; sK[li][t][5]=k1.y; sK[li][t][6]=k1.z; sK[li][t][7]=k1.w;
        sV[li][t][0]=v0.x; sV[li][t][1]=v0.y; sV[li][t][2]=v0.z; sV[li][t][3]=v0.w;
        sV[li][t][4]=v1.x; sV[li][t][5]=v1.y; sV[li][t][6]=v1.z; sV[li][t][7]=v1.w;
        q[0]=q0.x; q[1]=q0.y; q[2]=q0.z; q[3]=q0.w;
        q[4]=q1.x; q[5]=q1.y; q[6]=q1.z; q[7]=q1.w;
    }
    __syncthreads();

    float mx = -1e30f;
    for (int s = 0; s <= t; s++) {
        float d = 0.f;
        #pragma unroll
        for (int h = 0; h < 8; h++) d = fmaf(q[h], sK[li][s][h], d);
        d *= 0.25f;
        sS[li][t][s] = d;
        mx = fmaxf(mx, d);
    }
    float denom = 0.f;
    float acc[8];
    #pragma unroll
    for (int h = 0; h < 8; h++) acc[h] = 0.f;
    for (int s = 0; s <= t; s++) {
        float p = __expf(sS[li][t][s] - mx);
        denom += p;
        #pragma unroll
        for (int h = 0; h < 8; h++) acc[h] = fmaf(p, sV[li][s][h], acc[h]);
    }
    float inv = 1.f / denom;
    float4 o0 = make_float4(acc[0]*inv, acc[1]*inv, acc[2]*inv, acc[3]*inv);
    float4 o1 = make_float4(acc[4]*inv, acc[5]*inv, acc[6]*inv, acc[7]*inv);
    *(float4*)&g_AO[base]     = o0;
    *(float4*)&g_AO[base + 4] = o1;
}

// ---------------------------------------------------------------------------
// Kernel 3: output projection (bf16 3-term).  out = relu(AO @ Wo + bo)
// ---------------------------------------------------------------------------
__global__ __launch_bounds__(128) void out_gemm_tc(const float* __restrict__ Wo,
                                                   const float* __restrict__ bo,
                                                   float* __restrict__ out) {
    __shared__ uint32_t sAh[2][8*SPAD], sAl[2][8*SPAD];
    __shared__ uint32_t sBh[2][8*SPAD], sBl[2][8*SPAD];

    const int tid = threadIdx.x;
    const int lane = tid & 31;
    const int wid = tid >> 5;
    const int g = lane >> 2, t = lane & 3;
    const int wm = (wid >> 1) * 64, wn = (wid & 1) * 64;
    const int m0 = blockIdx.x * 128;

    const int ar  = tid >> 1;
    const int par = tid & 1;
    const int bkp = tid >> 4;
    const int bn0 = (tid & 15) * 8;
    const int bc4 = (tid & 15) >> 2;

    float acc[4][8][4];
    #pragma unroll
    for (int im = 0; im < 4; im++)
        #pragma unroll
        for (int in = 0; in < 8; in++)
            #pragma unroll
            for (int r = 0; r < 4; r++) acc[im][in][r] = 0.f;

    const int NIT = Dd / 16;   // 8 slabs

    float4 tr_a0, tr_a1, tr_a2, tr_a3, tr_b0, tr_b1, tr_b2, tr_b3;
    {
        int gk = par * 8;
        tr_a0 = *(const float4*)&g_AO[(size_t)(m0 + ar) * Dd + gk];
        tr_a1 = *(const float4*)&g_AO[(size_t)(m0 + ar) * Dd + gk + 4];
        tr_a2 = *(const float4*)&g_AO[(size_t)(m0 + ar + 64) * Dd + gk];
        tr_a3 = *(const float4*)&g_AO[(size_t)(m0 + ar + 64) * Dd + gk + 4];
        tr_b0 = *(const float4*)&Wo[(size_t)(2*bkp    ) * Dd + bn0];
        tr_b1 = *(const float4*)&Wo[(size_t)(2*bkp    ) * Dd + bn0 + 4];
        tr_b2 = *(const float4*)&Wo[(size_t)(2*bkp + 1) * Dd + bn0];
        tr_b3 = *(const float4*)&Wo[(size_t)(2*bkp + 1) * Dd + bn0 + 4];
    }
    STORE_TILE(0);
    __syncthreads();

    for (int it = 0; it < NIT; it++) {
        const int cur = it & 1;
        const bool has_next = (it + 1 < NIT);
        if (has_next) {
            int k0 = (it + 1) * 16;
            int gk = k0 + par * 8;
            tr_a0 = *(const float4*)&g_AO[(size_t)(m0 + ar) * Dd + gk];
            tr_a1 = *(const float4*)&g_AO[(size_t)(m0 + ar) * Dd + gk + 4];
            tr_a2 = *(const float4*)&g_AO[(size_t)(m0 + ar + 64) * Dd + gk];
            tr_a3 = *(const float4*)&g_AO[(size_t)(m0 + ar + 64) * Dd + gk + 4];
            tr_b0 = *(const float4*)&Wo[(size_t)(k0 + 2*bkp    ) * Dd + bn0];
            tr_b1 = *(const float4*)&Wo[(size_t)(k0 + 2*bkp    ) * Dd + bn0 + 4];
            tr_b2 = *(const float4*)&Wo[(size_t)(k0 + 2*bkp + 1) * Dd + bn0];
            tr_b3 = *(const float4*)&Wo[(size_t)(k0 + 2*bkp + 1) * Dd + bn0 + 4];
        }

        GEMM_COMPUTE(sAh[cur], sAl[cur], sBh[cur], sBl[cur]);

        if (has_next) {
            const int nxt = cur ^ 1;
            STORE_TILE(nxt);
        }
        __syncthreads();
    }

    #pragma unroll
    for (int im = 0; im < 4; im++) {
        int r0 = m0 + wm + im * 16 + g;
        #pragma unroll
        for (int in = 0; in < 8; in++) {
            int c = wn + in * 8 + 2 * t;
            float b0v = bo[c], b1v = bo[c + 1];
            float2 o;
            o.x = fmaxf(acc[im][in][0] + b0v, 0.f);
            o.y = fmaxf(acc[im][in][1] + b1v, 0.f);
            *(float2*)&out[(size_t)r0 * Dd + c] = o;
            o.x = fmaxf(acc[im][in][2] + b0v, 0.f);
            o.y = fmaxf(acc[im][in][3] + b1v, 0.f);
            *(float2*)&out[(size_t)(r0 + 8) * Dd + c] = o;
        }
    }
}

// ---------------------------------------------------------------------------
extern "C" void kernel_launch(void* const* d_in, const int* in_sizes, int n_in,
                              void* d_out, int out_size) {
    const float* X   = (const float*)d_in[0];
    const float* STE = (const float*)d_in[1];
    const float* Wq  = (const float*)d_in[2];
    const float* bq  = (const float*)d_in[3];
    const float* Wk  = (const float*)d_in[4];
    const float* bk  = (const float*)d_in[5];
    const float* Wv  = (const float*)d_in[6];
    const float* bv  = (const float*)d_in[7];
    const float* Wo  = (const float*)d_in[8];
    const float* bo  = (const float*)d_in[9];
    float* out = (float*)d_out;

    pack_w<<<128, 256>>>(Wq, bq, Wk, bk, Wv, bv);

    dim3 gA(MTOK / 128, QKVN / 128);        // 1024 x 3
    qkv_gemm_tc<<<gA, 128>>>(X, STE);

    attn_kernel<<<Bb * Nn * 8, 128>>>();    // 32768 instances, 2 per block

    out_gemm_tc<<<MTOK / 128, 128>>>(Wo, bo, out);
}

// round 14
// speedup vs baseline: 1.5683x; 1.1343x over previous
#include <cuda_runtime.h>
#include <cuda_bf16.h>
#include <cstdint>

// Problem shapes (fixed by the dataset)
#define Bb   8
#define Tt   64
#define Nn   256
#define Dd   128
#define MTOK (Bb*Tt*Nn)     // 131072 tokens
#define K2   256            // 2*D (concat input dim)
#define QKVN 384            // 3*D output cols of fused QKV GEMM

#define SPAD 136            // smem row stride in 4B words ([kpair][x] layout)

// Scratch (device globals; no allocation allowed)
__device__ float g_Wqkv[K2*QKVN];   // packed [256][384] = Wq|Wk|Wv
__device__ float g_bqkv[QKVN];
__device__ float g_Q[MTOK*Dd];
__device__ float g_K[MTOK*Dd];
__device__ float g_V[MTOK*Dd];
__device__ float g_AO[MTOK*Dd];

// ---------------------------------------------------------------------------
// bf16 double-split: x = hi + lo + O(2^-17 x). Pack k-pairs for m16n8k16.
__device__ __forceinline__ void split2(float x0, float x1, uint32_t& hi, uint32_t& lo) {
    __nv_bfloat16 h0 = __float2bfloat16(x0);
    __nv_bfloat16 h1 = __float2bfloat16(x1);
    __nv_bfloat16 l0 = __float2bfloat16(x0 - __bfloat162float(h0));
    __nv_bfloat16 l1 = __float2bfloat16(x1 - __bfloat162float(h1));
    __nv_bfloat162 hp = __halves2bfloat162(h0, h1);
    __nv_bfloat162 lp = __halves2bfloat162(l0, l1);
    hi = *reinterpret_cast<uint32_t*>(&hp);
    lo = *reinterpret_cast<uint32_t*>(&lp);
}

__device__ __forceinline__ void mma16(float* c, const uint32_t* a, const uint32_t* b) {
    asm volatile(
        "mma.sync.aligned.m16n8k16.row.col.f32.bf16.bf16.f32 "
        "{%0,%1,%2,%3}, {%4,%5,%6,%7}, {%8,%9}, {%0,%1,%2,%3};"
        : "+f"(c[0]), "+f"(c[1]), "+f"(c[2]), "+f"(c[3])
        : "r"(a[0]), "r"(a[1]), "r"(a[2]), "r"(a[3]),
          "r"(b[0]), "r"(b[1]));
}

// ---------------------------------------------------------------------------
// Kernel 0: pack Wq/Wk/Wv ([256,128] each, row-major) into g_Wqkv [256,384]
// ---------------------------------------------------------------------------
__global__ void pack_w(const float* __restrict__ Wq, const float* __restrict__ bq,
                       const float* __restrict__ Wk, const float* __restrict__ bk,
                       const float* __restrict__ Wv, const float* __restrict__ bv) {
    int i = blockIdx.x * blockDim.x + threadIdx.x;
    if (i < K2 * Dd) {
        int k = i / Dd, j = i % Dd;
        g_Wqkv[k*QKVN + j        ] = Wq[i];
        g_Wqkv[k*QKVN + Dd   + j ] = Wk[i];
        g_Wqkv[k*QKVN + 2*Dd + j ] = Wv[i];
    }
    if (i < Dd) {
        g_bqkv[i]        = bq[i];
        g_bqkv[Dd + i]   = bk[i];
        g_bqkv[2*Dd + i] = bv[i];
    }
}

// ---------------------------------------------------------------------------
// 3-term bf16 GEMM core.  BM=BN=128, BK=16, 256 threads, 8 warps (2x4),
// 64x32 per warp, m16n8k16.  Smem [kpair][x] (uint32 = bf16x2), stride SPAD.
// ---------------------------------------------------------------------------

// A store: thread owns row 'row', kpairs par*4..par*4+3 (k = par*8..par*8+7).
// Rotation by par keeps STS phases conflict-free.
__device__ __forceinline__ void storeA(uint32_t* sAh, uint32_t* sAl,
                                       int row, int par, float4 v0, float4 v1) {
    const float vv[8] = {v0.x, v0.y, v0.z, v0.w, v1.x, v1.y, v1.z, v1.w};
    #pragma unroll
    for (int ii = 0; ii < 4; ii++) {
        int q = (ii + 2*par) & 3;
        uint32_t h, l;
        split2(vv[2*q], vv[2*q + 1], h, l);
        sAh[(par*4 + q)*SPAD + row] = h;
        sAl[(par*4 + q)*SPAD + row] = l;
    }
}

// B store: thread owns kpair bkp, 4 consecutive cols bc0..bc0+3.
// r0 = k-even row float4, r1 = k-odd row float4 -> one STS.128 each for hi/lo.
__device__ __forceinline__ void storeB(uint32_t* sBh, uint32_t* sBl,
                                       int bkp, int bc0, float4 r0, float4 r1) {
    uint4 h4, l4;
    split2(r0.x, r1.x, h4.x, l4.x);
    split2(r0.y, r1.y, h4.y, l4.y);
    split2(r0.z, r1.z, h4.z, l4.z);
    split2(r0.w, r1.w, h4.w, l4.w);
    *(uint4*)&sBh[bkp*SPAD + bc0] = h4;
    *(uint4*)&sBl[bkp*SPAD + bc0] = l4;
}

#define GEMM_COMPUTE(sAh, sAl, sBh, sBl)                                     \
    {                                                                        \
        uint32_t Ah[4][4], Al[4][4], Bh[4][2], Bl[4][2];                     \
        _Pragma("unroll")                                                    \
        for (int im = 0; im < 4; im++) {                                     \
            int m = wm + im*16 + g;                                          \
            Ah[im][0] = (sAh)[ t   *SPAD + m    ];                           \
            Ah[im][1] = (sAh)[ t   *SPAD + m + 8];                           \
            Ah[im][2] = (sAh)[(t+4)*SPAD + m    ];                           \
            Ah[im][3] = (sAh)[(t+4)*SPAD + m + 8];                           \
            Al[im][0] = (sAl)[ t   *SPAD + m    ];                           \
            Al[im][1] = (sAl)[ t   *SPAD + m + 8];                           \
            Al[im][2] = (sAl)[(t+4)*SPAD + m    ];                           \
            Al[im][3] = (sAl)[(t+4)*SPAD + m + 8];                           \
        }                                                                    \
        _Pragma("unroll")                                                    \
        for (int in = 0; in < 4; in++) {                                     \
            int n = wn + in*8 + g;                                           \
            Bh[in][0] = (sBh)[ t   *SPAD + n];                               \
            Bh[in][1] = (sBh)[(t+4)*SPAD + n];                               \
            Bl[in][0] = (sBl)[ t   *SPAD + n];                               \
            Bl[in][1] = (sBl)[(t+4)*SPAD + n];                               \
        }                                                                    \
        _Pragma("unroll")                                                    \
        for (int im = 0; im < 4; im++)                                       \
            _Pragma("unroll")                                                \
            for (int in = 0; in < 4; in++) mma16(acc[im][in], Ah[im], Bh[in]);\
        _Pragma("unroll")                                                    \
        for (int im = 0; im < 4; im++)                                       \
            _Pragma("unroll")                                                \
            for (int in = 0; in < 4; in++) mma16(acc[im][in], Al[im], Bh[in]);\
        _Pragma("unroll")                                                    \
        for (int im = 0; im < 4; im++)                                       \
            _Pragma("unroll")                                                \
            for (int in = 0; in < 4; in++) mma16(acc[im][in], Ah[im], Bl[in]);\
    }

#define STORE_TILE(buf)                                                      \
    storeA(sAh[buf], sAl[buf], ar, par, tr_a0, tr_a1);                       \
    storeB(sBh[buf], sBl[buf], bkp, bc0, tr_b0, tr_b1);

// ---------------------------------------------------------------------------
// Kernel 1: QKV GEMM (bf16 3-term).  relu([X|STE] @ Wqkv + b) -> g_Q/g_K/g_V
// ---------------------------------------------------------------------------
__global__ __launch_bounds__(256, 2) void qkv_gemm_tc(const float* __restrict__ X,
                                                      const float* __restrict__ STE) {
    __shared__ uint32_t sAh[2][8*SPAD], sAl[2][8*SPAD];
    __shared__ uint32_t sBh[2][8*SPAD], sBl[2][8*SPAD];

    const int tid = threadIdx.x;
    const int lane = tid & 31;
    const int wid = tid >> 5;                 // 0..7
    const int g = lane >> 2, t = lane & 3;
    const int wm = (wid >> 2) * 64;           // 2 warps in M
    const int wn = (wid & 3) * 32;            // 4 warps in N
    const int m0 = blockIdx.x * 128;
    const int j0 = blockIdx.y * 128;

    // A loader: one row per thread, k = par*8..par*8+7
    const int ar  = tid >> 1;                 // 0..127
    const int par = tid & 1;
    // B loader: kpair bkp = warp id (0..7), cols bc0..bc0+3
    const int bkp = tid >> 5;
    const int bc0 = (tid & 31) * 4;

    float acc[4][4][4];
    #pragma unroll
    for (int im = 0; im < 4; im++)
        #pragma unroll
        for (int in = 0; in < 4; in++)
            #pragma unroll
            for (int r = 0; r < 4; r++) acc[im][in][r] = 0.f;

    const int NIT = K2 / 16;   // 16 slabs

    float4 tr_a0, tr_a1, tr_b0, tr_b1;
    // preload slab 0 (k0 = 0, inside X)
    {
        int gk = par * 8;
        tr_a0 = *(const float4*)&X[(size_t)(m0 + ar) * Dd + gk];
        tr_a1 = *(const float4*)&X[(size_t)(m0 + ar) * Dd + gk + 4];
        tr_b0 = *(const float4*)&g_Wqkv[(size_t)(2*bkp    ) * QKVN + j0 + bc0];
        tr_b1 = *(const float4*)&g_Wqkv[(size_t)(2*bkp + 1) * QKVN + j0 + bc0];
    }
    STORE_TILE(0);
    __syncthreads();

    for (int it = 0; it < NIT; it++) {
        const int cur = it & 1;
        const bool has_next = (it + 1 < NIT);
        if (has_next) {
            int k0 = (it + 1) * 16;
            const float* src = (k0 < Dd) ? X : STE;
            int gk = (k0 & (Dd - 1)) + par * 8;
            tr_a0 = *(const float4*)&src[(size_t)(m0 + ar) * Dd + gk];
            tr_a1 = *(const float4*)&src[(size_t)(m0 + ar) * Dd + gk + 4];
            tr_b0 = *(const float4*)&g_Wqkv[(size_t)(k0 + 2*bkp    ) * QKVN + j0 + bc0];
            tr_b1 = *(const float4*)&g_Wqkv[(size_t)(k0 + 2*bkp + 1) * QKVN + j0 + bc0];
        }

        GEMM_COMPUTE(sAh[cur], sAl[cur], sBh[cur], sBl[cur]);

        if (has_next) {
            const int nxt = cur ^ 1;
            STORE_TILE(nxt);
        }
        __syncthreads();
    }

    // epilogue: bias + relu; whole 128-col tile -> exactly one of Q/K/V
    float* dst = (j0 == 0) ? g_Q : ((j0 == Dd) ? g_K : g_V);
    #pragma unroll
    for (int im = 0; im < 4; im++) {
        int r0 = m0 + wm + im * 16 + g;
        #pragma unroll
        for (int in = 0; in < 4; in++) {
            int c = wn + in * 8 + 2 * t;   // local col, even
            float b0v = g_bqkv[j0 + c], b1v = g_bqkv[j0 + c + 1];
            float2 o;
            o.x = fmaxf(acc[im][in][0] + b0v, 0.f);
            o.y = fmaxf(acc[im][in][1] + b1v, 0.f);
            *(float2*)&dst[(size_t)r0 * Dd + c] = o;
            o.x = fmaxf(acc[im][in][2] + b0v, 0.f);
            o.y = fmaxf(acc[im][in][3] + b1v, 0.f);
            *(float2*)&dst[(size_t)(r0 + 8) * Dd + c] = o;
        }
    }
}

// ---------------------------------------------------------------------------
// Kernel 2: causal attention. 2 instances per 128-thread block. (fp32)
// ---------------------------------------------------------------------------
__global__ __launch_bounds__(128) void attn_kernel() {
    __shared__ float sK[2][64][9];
    __shared__ float sV[2][64][9];
    __shared__ float sS[2][64][65];

    const int li   = threadIdx.x >> 6;
    const int inst = blockIdx.x * 2 + li;
    const int b = inst >> 12;
    const int r = inst & 4095;
    const int n = r >> 4;
    const int c = r & 15;
    const int t = threadIdx.x & 63;

    const size_t base = ((((size_t)b * Tt + t) * Nn + n) * Dd) + (size_t)c * 8;

    float q[8];
    {
        float4 k0 = *(const float4*)&g_K[base];
        float4 k1 = *(const float4*)&g_K[base + 4];
        float4 v0 = *(const float4*)&g_V[base];
        float4 v1 = *(const float4*)&g_V[base + 4];
        float4 q0 = *(const float4*)&g_Q[base];
        float4 q1 = *(const float4*)&g_Q[base + 4];
        sK[li][t][0]=k0.x; sK[li][t][1]=k0.y; sK[li][t][2]=k0.z; sK[li][t][3]=k0.w;
        sK[li][t][4]=k1.x; sK[li][t][5]=k1.y; sK[li][t][6]=k1.z; sK[li][t][7]=k1.w;
        sV[li][t][0]=v0.x; sV[li][t][1]=v0.y; sV[li][t][2]=v0.z; sV[li][t][3]=v0.w;
        sV[li][t][4]=v1.x; sV[li][t][5]=v1.y; sV[li][t][6]=v1.z; sV[li][t][7]=v1.w;
        q[0]=q0.x; q[1]=q0.y; q[2]=q0.z; q[3]=q0.w;
        q[4]=q1.x; q[5]=q1.y; q[6]=q1.z; q[7]=q1.w;
    }
    __syncthreads();

    float mx = -1e30f;
    for (int s = 0; s <= t; s++) {
        float d = 0.f;
        #pragma unroll
        for (int h = 0; h < 8; h++) d = fmaf(q[h], sK[li][s][h], d);
        d *= 0.25f;
        sS[li][t][s] = d;
        mx = fmaxf(mx, d);
    }
    float denom = 0.f;
    float acc[8];
    #pragma unroll
    for (int h = 0; h < 8; h++) acc[h] = 0.f;
    for (int s = 0; s <= t; s++) {
        float p = __expf(sS[li][t][s] - mx);
        denom += p;
        #pragma unroll
        for (int h = 0; h < 8; h++) acc[h] = fmaf(p, sV[li][s][h], acc[h]);
    }
    float inv = 1.f / denom;
    float4 o0 = make_float4(acc[0]*inv, acc[1]*inv, acc[2]*inv, acc[3]*inv);
    float4 o1 = make_float4(acc[4]*inv, acc[5]*inv, acc[6]*inv, acc[7]*inv);
    *(float4*)&g_AO[base]     = o0;
    *(float4*)&g_AO[base + 4] = o1;
}

// ---------------------------------------------------------------------------
// Kernel 3: output projection (bf16 3-term).  out = relu(AO @ Wo + bo)
// ---------------------------------------------------------------------------
__global__ __launch_bounds__(256, 2) void out_gemm_tc(const float* __restrict__ Wo,
                                                      const float* __restrict__ bo,
                                                      float* __restrict__ out) {
    __shared__ uint32_t sAh[2][8*SPAD], sAl[2][8*SPAD];
    __shared__ uint32_t sBh[2][8*SPAD], sBl[2][8*SPAD];

    const int tid = threadIdx.x;
    const int lane = tid & 31;
    const int wid = tid >> 5;
    const int g = lane >> 2, t = lane & 3;
    const int wm = (wid >> 2) * 64;
    const int wn = (wid & 3) * 32;
    const int m0 = blockIdx.x * 128;

    const int ar  = tid >> 1;
    const int par = tid & 1;
    const int bkp = tid >> 5;
    const int bc0 = (tid & 31) * 4;

    float acc[4][4][4];
    #pragma unroll
    for (int im = 0; im < 4; im++)
        #pragma unroll
        for (int in = 0; in < 4; in++)
            #pragma unroll
            for (int r = 0; r < 4; r++) acc[im][in][r] = 0.f;

    const int NIT = Dd / 16;   // 8 slabs

    float4 tr_a0, tr_a1, tr_b0, tr_b1;
    {
        int gk = par * 8;
        tr_a0 = *(const float4*)&g_AO[(size_t)(m0 + ar) * Dd + gk];
        tr_a1 = *(const float4*)&g_AO[(size_t)(m0 + ar) * Dd + gk + 4];
        tr_b0 = *(const float4*)&Wo[(size_t)(2*bkp    ) * Dd + bc0];
        tr_b1 = *(const float4*)&Wo[(size_t)(2*bkp + 1) * Dd + bc0];
    }
    STORE_TILE(0);
    __syncthreads();

    for (int it = 0; it < NIT; it++) {
        const int cur = it & 1;
        const bool has_next = (it + 1 < NIT);
        if (has_next) {
            int k0 = (it + 1) * 16;
            int gk = k0 + par * 8;
            tr_a0 = *(const float4*)&g_AO[(size_t)(m0 + ar) * Dd + gk];
            tr_a1 = *(const float4*)&g_AO[(size_t)(m0 + ar) * Dd + gk + 4];
            tr_b0 = *(const float4*)&Wo[(size_t)(k0 + 2*bkp    ) * Dd + bc0];
            tr_b1 = *(const float4*)&Wo[(size_t)(k0 + 2*bkp + 1) * Dd + bc0];
        }

        GEMM_COMPUTE(sAh[cur], sAl[cur], sBh[cur], sBl[cur]);

        if (has_next) {
            const int nxt = cur ^ 1;
            STORE_TILE(nxt);
        }
        __syncthreads();
    }

    #pragma unroll
    for (int im = 0; im < 4; im++) {
        int r0 = m0 + wm + im * 16 + g;
        #pragma unroll
        for (int in = 0; in < 4; in++) {
            int c = wn + in * 8 + 2 * t;
            float b0v = bo[c], b1v = bo[c + 1];
            float2 o;
            o.x = fmaxf(acc[im][in][0] + b0v, 0.f);
            o.y = fmaxf(acc[im][in][1] + b1v, 0.f);
            *(float2*)&out[(size_t)r0 * Dd + c] = o;
            o.x = fmaxf(acc[im][in][2] + b0v, 0.f);
            o.y = fmaxf(acc[im][in][3] + b1v, 0.f);
            *(float2*)&out[(size_t)(r0 + 8) * Dd + c] = o;
        }
    }
}

// ---------------------------------------------------------------------------
extern "C" void kernel_launch(void* const* d_in, const int* in_sizes, int n_in,
                              void* d_out, int out_size) {
    const float* X   = (const float*)d_in[0];
    const float* STE = (const float*)d_in[1];
    const float* Wq  = (const float*)d_in[2];
    const float* bq  = (const float*)d_in[3];
    const float* Wk  = (const float*)d_in[4];
    const float* bk  = (const float*)d_in[5];
    const float* Wv  = (const float*)d_in[6];
    const float* bv  = (const float*)d_in[7];
    const float* Wo  = (const float*)d_in[8];
    const float* bo  = (const float*)d_in[9];
    float* out = (float*)d_out;

    pack_w<<<128, 256>>>(Wq, bq, Wk, bk, Wv, bv);

    dim3 gA(MTOK / 128, QKVN / 128);        // 1024 x 3
    qkv_gemm_tc<<<gA, 256>>>(X, STE);

    attn_kernel<<<Bb * Nn * 8, 128>>>();    // 32768 instances, 2 per block

    out_gemm_tc<<<MTOK / 128, 256>>>(Wo, bo, out);
}

// round 17
// speedup vs baseline: 1.7161x; 1.0943x over previous
#include <cuda_runtime.h>
#include <cuda_bf16.h>
#include <cstdint>

// Problem shapes (fixed by the dataset)
#define Bb   8
#define Tt   64
#define Nn   256
#define Dd   128
#define MTOK (Bb*Tt*Nn)     // 131072 tokens
#define K2   256            // 2*D (concat input dim)
#define QKVN 384            // 3*D output cols of fused QKV GEMM

#define SPAD 136            // smem row stride in 4B words ([kpair][x] layout)

// Scratch (device globals; no allocation allowed)
__device__ float g_Wqkv[K2*QKVN];   // packed [256][384] = Wq|Wk|Wv
__device__ float g_bqkv[QKVN];
__device__ float g_Q[MTOK*Dd];
__device__ float g_K[MTOK*Dd];
__device__ float g_V[MTOK*Dd];
__device__ float g_AO[MTOK*Dd];

// ---------------------------------------------------------------------------
// bf16 double-split: x = hi + lo + O(2^-17 x). Pack k-pairs for m16n8k16.
__device__ __forceinline__ void split2(float x0, float x1, uint32_t& hi, uint32_t& lo) {
    __nv_bfloat16 h0 = __float2bfloat16(x0);
    __nv_bfloat16 h1 = __float2bfloat16(x1);
    __nv_bfloat16 l0 = __float2bfloat16(x0 - __bfloat162float(h0));
    __nv_bfloat16 l1 = __float2bfloat16(x1 - __bfloat162float(h1));
    __nv_bfloat162 hp = __halves2bfloat162(h0, h1);
    __nv_bfloat162 lp = __halves2bfloat162(l0, l1);
    hi = *reinterpret_cast<uint32_t*>(&hp);
    lo = *reinterpret_cast<uint32_t*>(&lp);
}

__device__ __forceinline__ void mma16(float* c, const uint32_t* a, const uint32_t* b) {
    asm volatile(
        "mma.sync.aligned.m16n8k16.row.col.f32.bf16.bf16.f32 "
        "{%0,%1,%2,%3}, {%4,%5,%6,%7}, {%8,%9}, {%0,%1,%2,%3};"
        : "+f"(c[0]), "+f"(c[1]), "+f"(c[2]), "+f"(c[3])
        : "r"(a[0]), "r"(a[1]), "r"(a[2]), "r"(a[3]),
          "r"(b[0]), "r"(b[1]));
}

// ---------------------------------------------------------------------------
// Kernel 0: pack Wq/Wk/Wv ([256,128] each, row-major) into g_Wqkv [256,384]
// ---------------------------------------------------------------------------
__global__ void pack_w(const float* __restrict__ Wq, const float* __restrict__ bq,
                       const float* __restrict__ Wk, const float* __restrict__ bk,
                       const float* __restrict__ Wv, const float* __restrict__ bv) {
    int i = blockIdx.x * blockDim.x + threadIdx.x;
    if (i < K2 * Dd) {
        int k = i / Dd, j = i % Dd;
        g_Wqkv[k*QKVN + j        ] = Wq[i];
        g_Wqkv[k*QKVN + Dd   + j ] = Wk[i];
        g_Wqkv[k*QKVN + 2*Dd + j ] = Wv[i];
    }
    if (i < Dd) {
        g_bqkv[i]        = bq[i];
        g_bqkv[Dd + i]   = bk[i];
        g_bqkv[2*Dd + i] = bv[i];
    }
}

// ---------------------------------------------------------------------------
// 3-term bf16 GEMM core.  BM=BN=128, BK=16, 256 threads, 8 warps (2x4),
// 64x32 per warp, m16n8k16.  Smem [kpair][x] (uint32 = bf16x2), stride SPAD.
// ---------------------------------------------------------------------------

// A store: thread owns row 'row', kpairs par*4..par*4+3 (k = par*8..par*8+7).
// Rotation by par keeps STS phases conflict-free.
__device__ __forceinline__ void storeA(uint32_t* sAh, uint32_t* sAl,
                                       int row, int par, float4 v0, float4 v1) {
    const float vv[8] = {v0.x, v0.y, v0.z, v0.w, v1.x, v1.y, v1.z, v1.w};
    #pragma unroll
    for (int ii = 0; ii < 4; ii++) {
        int q = (ii + 2*par) & 3;
        uint32_t h, l;
        split2(vv[2*q], vv[2*q + 1], h, l);
        sAh[(par*4 + q)*SPAD + row] = h;
        sAl[(par*4 + q)*SPAD + row] = l;
    }
}

// B store: thread owns kpair bkp, 4 consecutive cols bc0..bc0+3.
// r0 = k-even row float4, r1 = k-odd row float4 -> one STS.128 each for hi/lo.
__device__ __forceinline__ void storeB(uint32_t* sBh, uint32_t* sBl,
                                       int bkp, int bc0, float4 r0, float4 r1) {
    uint4 h4, l4;
    split2(r0.x, r1.x, h4.x, l4.x);
    split2(r0.y, r1.y, h4.y, l4.y);
    split2(r0.z, r1.z, h4.z, l4.z);
    split2(r0.w, r1.w, h4.w, l4.w);
    *(uint4*)&sBh[bkp*SPAD + bc0] = h4;
    *(uint4*)&sBl[bkp*SPAD + bc0] = l4;
}

#define GEMM_COMPUTE(sAh, sAl, sBh, sBl)                                     \
    {                                                                        \
        uint32_t Ah[4][4], Al[4][4], Bh[4][2], Bl[4][2];                     \
        _Pragma("unroll")                                                    \
        for (int im = 0; im < 4; im++) {                                     \
            int m = wm + im*16 + g;                                          \
            Ah[im][0] = (sAh)[ t   *SPAD + m    ];                           \
            Ah[im][1] = (sAh)[ t   *SPAD + m + 8];                           \
            Ah[im][2] = (sAh)[(t+4)*SPAD + m    ];                           \
            Ah[im][3] = (sAh)[(t+4)*SPAD + m + 8];                           \
            Al[im][0] = (sAl)[ t   *SPAD + m    ];                           \
            Al[im][1] = (sAl)[ t   *SPAD + m + 8];                           \
            Al[im][2] = (sAl)[(t+4)*SPAD + m    ];                           \
            Al[im][3] = (sAl)[(t+4)*SPAD + m + 8];                           \
        }                                                                    \
        _Pragma("unroll")                                                    \
        for (int in = 0; in < 4; in++) {                                     \
            int n = wn + in*8 + g;                                           \
            Bh[in][0] = (sBh)[ t   *SPAD + n];                               \
            Bh[in][1] = (sBh)[(t+4)*SPAD + n];                               \
            Bl[in][0] = (sBl)[ t   *SPAD + n];                               \
            Bl[in][1] = (sBl)[(t+4)*SPAD + n];                               \
        }                                                                    \
        _Pragma("unroll")                                                    \
        for (int im = 0; im < 4; im++)                                       \
            _Pragma("unroll")                                                \
            for (int in = 0; in < 4; in++) mma16(acc[im][in], Ah[im], Bh[in]);\
        _Pragma("unroll")                                                    \
        for (int im = 0; im < 4; im++)                                       \
            _Pragma("unroll")                                                \
            for (int in = 0; in < 4; in++) mma16(acc[im][in], Al[im], Bh[in]);\
        _Pragma("unroll")                                                    \
        for (int im = 0; im < 4; im++)                                       \
            _Pragma("unroll")                                                \
            for (int in = 0; in < 4; in++) mma16(acc[im][in], Ah[im], Bl[in]);\
    }

#define STORE_TILE(buf)                                                      \
    storeA(sAh[buf], sAl[buf], ar, par, tr_a0, tr_a1);                       \
    storeB(sBh[buf], sBl[buf], bkp, bc0, tr_b0, tr_b1);

// ---------------------------------------------------------------------------
// Kernel 1: QKV GEMM (bf16 3-term).  relu([X|STE] @ Wqkv + b) -> g_Q/g_K/g_V
// ---------------------------------------------------------------------------
__global__ __launch_bounds__(256, 2) void qkv_gemm_tc(const float* __restrict__ X,
                                                      const float* __restrict__ STE) {
    __shared__ uint32_t sAh[2][8*SPAD], sAl[2][8*SPAD];
    __shared__ uint32_t sBh[2][8*SPAD], sBl[2][8*SPAD];

    const int tid = threadIdx.x;
    const int lane = tid & 31;
    const int wid = tid >> 5;                 // 0..7
    const int g = lane >> 2, t = lane & 3;
    const int wm = (wid >> 2) * 64;           // 2 warps in M
    const int wn = (wid & 3) * 32;            // 4 warps in N
    const int m0 = blockIdx.x * 128;
    const int j0 = blockIdx.y * 128;

    // A loader: one row per thread, k = par*8..par*8+7
    const int ar  = tid >> 1;                 // 0..127
    const int par = tid & 1;
    // B loader: kpair bkp = warp id (0..7), cols bc0..bc0+3
    const int bkp = tid >> 5;
    const int bc0 = (tid & 31) * 4;

    float acc[4][4][4];
    #pragma unroll
    for (int im = 0; im < 4; im++)
        #pragma unroll
        for (int in = 0; in < 4; in++)
            #pragma unroll
            for (int r = 0; r < 4; r++) acc[im][in][r] = 0.f;

    const int NIT = K2 / 16;   // 16 slabs

    float4 tr_a0, tr_a1, tr_b0, tr_b1;
    // preload slab 0 (k0 = 0, inside X)
    {
        int gk = par * 8;
        tr_a0 = *(const float4*)&X[(size_t)(m0 + ar) * Dd + gk];
        tr_a1 = *(const float4*)&X[(size_t)(m0 + ar) * Dd + gk + 4];
        tr_b0 = *(const float4*)&g_Wqkv[(size_t)(2*bkp    ) * QKVN + j0 + bc0];
        tr_b1 = *(const float4*)&g_Wqkv[(size_t)(2*bkp + 1) * QKVN + j0 + bc0];
    }
    STORE_TILE(0);
    __syncthreads();

    for (int it = 0; it < NIT; it++) {
        const int cur = it & 1;
        const bool has_next = (it + 1 < NIT);
        if (has_next) {
            int k0 = (it + 1) * 16;
            const float* src = (k0 < Dd) ? X : STE;
            int gk = (k0 & (Dd - 1)) + par * 8;
            tr_a0 = *(const float4*)&src[(size_t)(m0 + ar) * Dd + gk];
            tr_a1 = *(const float4*)&src[(size_t)(m0 + ar) * Dd + gk + 4];
            tr_b0 = *(const float4*)&g_Wqkv[(size_t)(k0 + 2*bkp    ) * QKVN + j0 + bc0];
            tr_b1 = *(const float4*)&g_Wqkv[(size_t)(k0 + 2*bkp + 1) * QKVN + j0 + bc0];
        }

        GEMM_COMPUTE(sAh[cur], sAl[cur], sBh[cur], sBl[cur]);

        if (has_next) {
            const int nxt = cur ^ 1;
            STORE_TILE(nxt);
        }
        __syncthreads();
    }

    // epilogue: bias + relu; whole 128-col tile -> exactly one of Q/K/V
    float* dst = (j0 == 0) ? g_Q : ((j0 == Dd) ? g_K : g_V);
    #pragma unroll
    for (int im = 0; im < 4; im++) {
        int r0 = m0 + wm + im * 16 + g;
        #pragma unroll
        for (int in = 0; in < 4; in++) {
            int c = wn + in * 8 + 2 * t;   // local col, even
            float b0v = g_bqkv[j0 + c], b1v = g_bqkv[j0 + c + 1];
            float2 o;
            o.x = fmaxf(acc[im][in][0] + b0v, 0.f);
            o.y = fmaxf(acc[im][in][1] + b1v, 0.f);
            *(float2*)&dst[(size_t)r0 * Dd + c] = o;
            o.x = fmaxf(acc[im][in][2] + b0v, 0.f);
            o.y = fmaxf(acc[im][in][3] + b1v, 0.f);
            *(float2*)&dst[(size_t)(r0 + 8) * Dd + c] = o;
        }
    }
}

// ---------------------------------------------------------------------------
// Kernel 2: causal attention, single-pass softmax (no max shift — scores are
// small: Q,K are relu'd projections, dot/4 << 80 so __expf cannot overflow).
// 2 instances per 128-thread block; K/V rows in smem as float4 (broadcast LDS).
// ---------------------------------------------------------------------------
__global__ __launch_bounds__(128) void attn_kernel() {
    __shared__ float4 sK[2][64][2];
    __shared__ float4 sV[2][64][2];

    const int li   = threadIdx.x >> 6;
    const int inst = blockIdx.x * 2 + li;
    const int b = inst >> 12;
    const int r = inst & 4095;
    const int n = r >> 4;
    const int c = r & 15;
    const int t = threadIdx.x & 63;

    const size_t base = ((((size_t)b * Tt + t) * Nn + n) * Dd) + (size_t)c * 8;

    float q[8];
    {
        float4 k0 = *(const float4*)&g_K[base];
        float4 k1 = *(const float4*)&g_K[base + 4];
        float4 v0 = *(const float4*)&g_V[base];
        float4 v1 = *(const float4*)&g_V[base + 4];
        float4 q0 = *(const float4*)&g_Q[base];
        float4 q1 = *(const float4*)&g_Q[base + 4];
        sK[li][t][0] = k0;  sK[li][t][1] = k1;
        sV[li][t][0] = v0;  sV[li][t][1] = v1;
        q[0]=q0.x; q[1]=q0.y; q[2]=q0.z; q[3]=q0.w;
        q[4]=q1.x; q[5]=q1.y; q[6]=q1.z; q[7]=q1.w;
    }
    __syncthreads();

    float denom = 0.f;
    float acc[8];
    #pragma unroll
    for (int h = 0; h < 8; h++) acc[h] = 0.f;

    for (int s = 0; s <= t; s++) {
        float4 ka = sK[li][s][0];
        float4 kb = sK[li][s][1];
        float d = q[0]*ka.x + q[1]*ka.y + q[2]*ka.z + q[3]*ka.w
                + q[4]*kb.x + q[5]*kb.y + q[6]*kb.z + q[7]*kb.w;
        float p = __expf(d * 0.25f);
        float4 va = sV[li][s][0];
        float4 vb = sV[li][s][1];
        denom += p;
        acc[0] = fmaf(p, va.x, acc[0]);
        acc[1] = fmaf(p, va.y, acc[1]);
        acc[2] = fmaf(p, va.z, acc[2]);
        acc[3] = fmaf(p, va.w, acc[3]);
        acc[4] = fmaf(p, vb.x, acc[4]);
        acc[5] = fmaf(p, vb.y, acc[5]);
        acc[6] = fmaf(p, vb.z, acc[6]);
        acc[7] = fmaf(p, vb.w, acc[7]);
    }

    float inv = 1.f / denom;
    float4 o0 = make_float4(acc[0]*inv, acc[1]*inv, acc[2]*inv, acc[3]*inv);
    float4 o1 = make_float4(acc[4]*inv, acc[5]*inv, acc[6]*inv, acc[7]*inv);
    *(float4*)&g_AO[base]     = o0;
    *(float4*)&g_AO[base + 4] = o1;
}

// ---------------------------------------------------------------------------
// Kernel 3: output projection (bf16 3-term).  out = relu(AO @ Wo + bo)
// ---------------------------------------------------------------------------
__global__ __launch_bounds__(256, 2) void out_gemm_tc(const float* __restrict__ Wo,
                                                      const float* __restrict__ bo,
                                                      float* __restrict__ out) {
    __shared__ uint32_t sAh[2][8*SPAD], sAl[2][8*SPAD];
    __shared__ uint32_t sBh[2][8*SPAD], sBl[2][8*SPAD];

    const int tid = threadIdx.x;
    const int lane = tid & 31;
    const int wid = tid >> 5;
    const int g = lane >> 2, t = lane & 3;
    const int wm = (wid >> 2) * 64;
    const int wn = (wid & 3) * 32;
    const int m0 = blockIdx.x * 128;

    const int ar  = tid >> 1;
    const int par = tid & 1;
    const int bkp = tid >> 5;
    const int bc0 = (tid & 31) * 4;

    float acc[4][4][4];
    #pragma unroll
    for (int im = 0; im < 4; im++)
        #pragma unroll
        for (int in = 0; in < 4; in++)
            #pragma unroll
            for (int r = 0; r < 4; r++) acc[im][in][r] = 0.f;

    const int NIT = Dd / 16;   // 8 slabs

    float4 tr_a0, tr_a1, tr_b0, tr_b1;
    {
        int gk = par * 8;
        tr_a0 = *(const float4*)&g_AO[(size_t)(m0 + ar) * Dd + gk];
        tr_a1 = *(const float4*)&g_AO[(size_t)(m0 + ar) * Dd + gk + 4];
        tr_b0 = *(const float4*)&Wo[(size_t)(2*bkp    ) * Dd + bc0];
        tr_b1 = *(const float4*)&Wo[(size_t)(2*bkp + 1) * Dd + bc0];
    }
    STORE_TILE(0);
    __syncthreads();

    for (int it = 0; it < NIT; it++) {
        const int cur = it & 1;
        const bool has_next = (it + 1 < NIT);
        if (has_next) {
            int k0 = (it + 1) * 16;
            int gk = k0 + par * 8;
            tr_a0 = *(const float4*)&g_AO[(size_t)(m0 + ar) * Dd + gk];
            tr_a1 = *(const float4*)&g_AO[(size_t)(m0 + ar) * Dd + gk + 4];
            tr_b0 = *(const float4*)&Wo[(size_t)(k0 + 2*bkp    ) * Dd + bc0];
            tr_b1 = *(const float4*)&Wo[(size_t)(k0 + 2*bkp + 1) * Dd + bc0];
        }

        GEMM_COMPUTE(sAh[cur], sAl[cur], sBh[cur], sBl[cur]);

        if (has_next) {
            const int nxt = cur ^ 1;
            STORE_TILE(nxt);
        }
        __syncthreads();
    }

    #pragma unroll
    for (int im = 0; im < 4; im++) {
        int r0 = m0 + wm + im * 16 + g;
        #pragma unroll
        for (int in = 0; in < 4; in++) {
            int c = wn + in * 8 + 2 * t;
            float b0v = bo[c], b1v = bo[c + 1];
            float2 o;
            o.x = fmaxf(acc[im][in][0] + b0v, 0.f);
            o.y = fmaxf(acc[im][in][1] + b1v, 0.f);
            *(float2*)&out[(size_t)r0 * Dd + c] = o;
            o.x = fmaxf(acc[im][in][2] + b0v, 0.f);
            o.y = fmaxf(acc[im][in][3] + b1v, 0.f);
            *(float2*)&out[(size_t)(r0 + 8) * Dd + c] = o;
        }
    }
}

// ---------------------------------------------------------------------------
extern "C" void kernel_launch(void* const* d_in, const int* in_sizes, int n_in,
                              void* d_out, int out_size) {
    const float* X   = (const float*)d_in[0];
    const float* STE = (const float*)d_in[1];
    const float* Wq  = (const float*)d_in[2];
    const float* bq  = (const float*)d_in[3];
    const float* Wk  = (const float*)d_in[4];
    const float* bk  = (const float*)d_in[5];
    const float* Wv  = (const float*)d_in[6];
    const float* bv  = (const float*)d_in[7];
    const float* Wo  = (const float*)d_in[8];
    const float* bo  = (const float*)d_in[9];
    float* out = (float*)d_out;

    pack_w<<<128, 256>>>(Wq, bq, Wk, bk, Wv, bv);

    dim3 gA(MTOK / 128, QKVN / 128);        // 1024 x 3
    qkv_gemm_tc<<<gA, 256>>>(X, STE);

    attn_kernel<<<Bb * Nn * 8, 128>>>();    // 32768 instances, 2 per block

    out_gemm_tc<<<MTOK / 128, 256>>>(Wo, bo, out);
}